// round 16
// baseline (speedup 1.0000x reference)
#include <cuda_runtime.h>
#include <cuda_fp16.h>
#include <math.h>
#include <stdint.h>

#define NEDGES 131072
#define FEAT   120
#define NS     512
#define KP     1344

// -------- static device scratch (allocation-free rule) --------
__device__ float  g_r[NEDGES];
__device__ __half g_embhl[(size_t)NEDGES * 512];    // [E][hi256|pad]
__device__ __half g_h1hl [(size_t)NEDGES * 2048];   // [E][hi1024|pad]
__device__ float  g_df   [(size_t)NEDGES * NS];
__device__ __half g_Phl  [(size_t)NEDGES * 2688];   // [E][hi1344|pad]
__device__ float  g_mixed[(size_t)NEDGES * NS];
__device__ __half g_reghl[(size_t)NEDGES * 1024];   // [E][hi512|pad]
// transposed weights: [N rows][hiK|loK] (lo planes unused, stride kept)
__device__ __half g_WcatT[(size_t)512  * 2688];
__device__ __half g_df1T [(size_t)1024 * 512];
__device__ __half g_df2T [(size_t)512  * 2048];
__device__ __half g_mi1T [(size_t)1024 * 1024];
__device__ __half g_mi2T [(size_t)1024 * 2048];

__device__ __forceinline__ uint32_t smem_u32(const void* p) {
    uint32_t a;
    asm("{ .reg .u64 t; cvta.to.shared.u64 t, %1; cvt.u32.u64 %0, t; }" : "=r"(a) : "l"(p));
    return a;
}
__device__ __forceinline__ void cp16(uint32_t s, const void* g) {
    asm volatile("cp.async.cg.shared.global [%0], [%1], 16;" :: "r"(s), "l"(g) : "memory");
}
__device__ __forceinline__ void ldm4(uint32_t* r, uint32_t addr) {
    asm volatile("ldmatrix.sync.aligned.m8n8.x4.shared.b16 {%0,%1,%2,%3}, [%4];"
                 : "=r"(r[0]), "=r"(r[1]), "=r"(r[2]), "=r"(r[3]) : "r"(addr));
}
__device__ __forceinline__ void mma16816(float* c, const uint32_t* a, uint32_t b0, uint32_t b1) {
    asm volatile("mma.sync.aligned.m16n8k16.row.col.f32.f16.f16.f32 "
                 "{%0,%1,%2,%3}, {%4,%5,%6,%7}, {%8,%9}, {%0,%1,%2,%3};"
                 : "+f"(c[0]), "+f"(c[1]), "+f"(c[2]), "+f"(c[3])
                 : "r"(a[0]), "r"(a[1]), "r"(a[2]), "r"(a[3]), "r"(b0), "r"(b1));
}

// ---------------- kernel: edge geometry -> r ----------------
__global__ void geom_kernel(const float* __restrict__ pos,
                            const float* __restrict__ cell,
                            const float* __restrict__ shift,
                            const int* __restrict__ ei,
                            const int* __restrict__ bvec) {
    int e = blockIdx.x * blockDim.x + threadIdx.x;
    if (e >= NEDGES) return;
    int src = ei[e];
    int dst = ei[NEDGES + e];
    int b = bvec[src];
    const float* C = cell + (size_t)b * 9;
    float s0 = shift[e * 3 + 0], s1 = shift[e * 3 + 1], s2 = shift[e * 3 + 2];
    float t0 = s0 * C[0] + s1 * C[3] + s2 * C[6];
    float t1 = s0 * C[1] + s1 * C[4] + s2 * C[7];
    float t2 = s0 * C[2] + s1 * C[5] + s2 * C[8];
    float dx = pos[dst * 3 + 0] - pos[src * 3 + 0] + t0;
    float dy = pos[dst * 3 + 1] - pos[src * 3 + 1] + t1;
    float dz = pos[dst * 3 + 2] - pos[src * 3 + 2] + t2;
    float dist = sqrtf(dx * dx + dy * dy + dz * dz);
    g_r[e] = 1.0f / (dist + 1e-6f);
}

// ---------------- radial embedding (hi fp16 only) ----------------
__global__ void emb_kernel() {
    int e = blockIdx.x;
    int k = threadIdx.x;   // 0..255
    float r = g_r[e];
    float amp = sqrtf(2.0f / 7.0f) / r;
    float ph = 3.14159265358979323846f * r / 7.0f;
    float x = amp * sinf((float)(k + 1) * ph);
    g_embhl[(size_t)e * 512 + k] = __float2half_rn(x);
}

// ---------------- symmetrized Wcat, transposed (hi only) ----------------
__global__ void wcat_kernel(const float* __restrict__ W0,
                            const float* __restrict__ W1,
                            const float* __restrict__ W2) {
    int idx = blockIdx.x * blockDim.x + threadIdx.x;
    if (idx >= KP * NS) return;
    int k = idx >> 9;
    int n = idx & 511;
    float fan = sqrtf(1344.0f);
    float v;
    if (k < 1024) {
        int u = k >> 5, vv = k & 31;
        v = (W0[(size_t)(u * 32 + vv) * NS + n] + W0[(size_t)(vv * 32 + u) * NS + n]) * (0.5f / fan);
    } else if (k < 1280) {
        int t = k - 1024;
        int u = t >> 4, vv = t & 15;
        v = (W1[(size_t)(u * 16 + vv) * NS + n] + W1[(size_t)(vv * 16 + u) * NS + n]) * (0.5f / (fan * sqrtf(3.0f)));
    } else {
        int t = k - 1280;
        int u = t >> 3, vv = t & 7;
        v = (W2[(size_t)(u * 8 + vv) * NS + n] + W2[(size_t)(vv * 8 + u) * NS + n]) * (0.5f / (fan * sqrtf(5.0f)));
    }
    g_WcatT[(size_t)n * 2688 + k] = __float2half_rn(v);
}

// ---------------- weight transpose, hi only ----------------
__global__ void wt_convert_hi(const float* __restrict__ W, __half* __restrict__ out,
                              int K, int N) {
    int idx = blockIdx.x * blockDim.x + threadIdx.x;
    if (idx >= K * N) return;
    int n = idx / K, k = idx - n * K;
    out[(size_t)n * 2 * K + k] = __float2half_rn(W[(size_t)k * N + n]);
}

// ---------------- outer products P (hi only) ----------------
__global__ void pbuild_kernel(const float* __restrict__ nodes,
                              const int* __restrict__ ei) {
    int e = blockIdx.x;
    int tid = threadIdx.x;   // 128
    __shared__ float xs[FEAT];
    __shared__ float xd[FEAT];
    int src = ei[e];
    int dst = ei[NEDGES + e];
    if (tid < FEAT) {
        xs[tid] = nodes[(size_t)src * FEAT + tid];
        xd[tid] = nodes[(size_t)dst * FEAT + tid];
    }
    __syncthreads();
    __half* Pe = g_Phl + (size_t)e * 2688;
    #pragma unroll
    for (int it = 0; it < 11; it++) {
        int idx = tid + it * 128;
        if (idx >= KP) break;
        float v;
        if (idx < 1024) {
            int u = idx >> 5, w = idx & 31;
            v = xs[u] * xd[w];
        } else if (idx < 1280) {
            int t = idx - 1024;
            int u = t >> 4, w = t & 15;
            const float* a = xs + 32 + u * 3;
            const float* b = xd + 32 + w * 3;
            v = a[0] * b[0] + a[1] * b[1] + a[2] * b[2];
        } else {
            int t = idx - 1280;
            int u = t >> 3, w = t & 7;
            const float* a = xs + 80 + u * 5;
            const float* b = xd + 80 + w * 5;
            v = a[0] * b[0] + a[1] * b[1] + a[2] * b[2] + a[3] * b[3] + a[4] * b[4];
        }
        Pe[idx] = __float2half_rn(v);
    }
}

// ====== HMMA GEMM: CTA 64x128, 8 warps of 32x32, super-chunks (BK=64), 3 stages, occ 3 ======
// 24 warps/SM (6/SMSP). Pure fp16 (SPLIT=1). A [M][K stride 2K], B [N][K stride 2K].
// Stage layout: [A0 4K][B0 8K][A1 4K][B1 8K] = 24KB; 3 stages = 72KB.
// MODE: 0 = fp32 out, 2 = fused head, 3 = fp16 hi plane only
#define STAGE_BYTES 24576
#define SMEMSZ (3 * STAGE_BYTES)

template<int MODE, bool BIAS, bool SILU, int SPLIT>
__global__ __launch_bounds__(256, 3)
void hgemm(const __half* __restrict__ A, const __half* __restrict__ B,
           const float* __restrict__ bias, const float* __restrict__ wv,
           float* __restrict__ outF, __half* __restrict__ outHL,
           int K, int Ntot) {
    extern __shared__ __align__(16) char smem[];
    const uint32_t sbase = smem_u32(smem);
    const int tid = threadIdx.x;
    const int lane = tid & 31;
    const int wid = tid >> 5;
    const int wm = wid & 1;        // 2 warps along M (32 rows each)
    const int wn = wid >> 1;       // 4 warps along N (32 cols each)
    const int m0 = blockIdx.y << 6;
    const int n0 = blockIdx.x << 7;
    const int A2K = 2 * K;
    const size_t strB = (size_t)A2K * sizeof(__half);
    const int nsuper = (SPLIT * K) >> 6;

    float acc[2][4][4];
    #pragma unroll
    for (int i = 0; i < 2; i++)
        #pragma unroll
        for (int j = 0; j < 4; j++)
            #pragma unroll
            for (int q = 0; q < 4; q++) acc[i][j][q] = 0.0f;

    // load one 32-wide sub-chunk into half h of stage s (256 threads)
    // sub layout: A (64x64B = 4KB) then B (128x64B = 8KB)
    auto load_sub = [&](int s, int h, int c) {
        int kg = c << 5;
        int seg = kg / K;
        int kin = kg - seg * K;
        int acol = kin + (seg == 2 ? K : 0);
        int bcol = kin + (seg == 1 ? K : 0);
        const char* Ag = (const char*)(A + (size_t)m0 * A2K + acol);
        const char* Bg = (const char*)(B + (size_t)n0 * A2K + bcol);
        uint32_t sA = sbase + (uint32_t)(s * STAGE_BYTES + h * 12288);
        uint32_t sB = sA + 4096;
        {   // A: 64 rows, 1 cp16 per thread
            int row = tid >> 2;
            int ch = tid & 3;
            uint32_t sw = (uint32_t)((ch ^ ((row >> 1) & 3)) << 4);
            cp16(sA + (uint32_t)(row * 64) + sw, Ag + (size_t)row * strB + ch * 16);
        }
        #pragma unroll
        for (int i = 0; i < 2; i++) {   // B: 128 rows
            int idx = tid + (i << 8);
            int row = idx >> 2;
            int ch = idx & 3;
            uint32_t sw = (uint32_t)((ch ^ ((row >> 1) & 3)) << 4);
            cp16(sB + (uint32_t)(row * 64) + sw, Bg + (size_t)row * strB + ch * 16);
        }
    };
    auto load_super = [&](int s, int cs) {
        load_sub(s, 0, 2 * cs);
        load_sub(s, 1, 2 * cs + 1);
    };

    auto compute_sub = [&](int s, int h) {
        const uint32_t sA = sbase + (uint32_t)(s * STAGE_BYTES + h * 12288);
        const uint32_t sB = sA + 4096;
        #pragma unroll
        for (int kk = 0; kk < 2; kk++) {
            uint32_t a[2][4];
            #pragma unroll
            for (int mi = 0; mi < 2; mi++) {
                int r = wm * 32 + mi * 16 + (lane & 15);
                int ch = 2 * kk + (lane >> 4);
                ldm4(a[mi], sA + (uint32_t)(r * 64 + ((ch ^ ((r >> 1) & 3)) << 4)));
            }
            uint32_t b[2][4];
            #pragma unroll
            for (int nh = 0; nh < 2; nh++) {
                int r = wn * 32 + nh * 16 + (lane & 15);
                int ch = 2 * kk + (lane >> 4);
                ldm4(b[nh], sB + (uint32_t)(r * 64 + ((ch ^ ((r >> 1) & 3)) << 4)));
            }
            #pragma unroll
            for (int mi = 0; mi < 2; mi++)
                #pragma unroll
                for (int ni = 0; ni < 4; ni++)
                    mma16816(acc[mi][ni], a[mi], b[ni >> 1][ni & 1], b[ni >> 1][(ni & 1) + 2]);
        }
    };

    load_super(0, 0);
    asm volatile("cp.async.commit_group;" ::: "memory");
    load_super(1, 1);
    asm volatile("cp.async.commit_group;" ::: "memory");

    for (int cs = 0; cs < nsuper; cs++) {
        asm volatile("cp.async.wait_group 1;" ::: "memory");
        __syncthreads();
        if (cs + 2 < nsuper) load_super((cs + 2) % 3, cs + 2);
        asm volatile("cp.async.commit_group;" ::: "memory");
        compute_sub(cs % 3, 0);
        compute_sub(cs % 3, 1);
    }

    // ---------------- epilogue: direct register -> global ----------------
    float bi0[4], bi1[4], wv0[4], wv1[4];
    #pragma unroll
    for (int ni = 0; ni < 4; ni++) {
        int n = n0 + wn * 32 + ni * 8 + (lane & 3) * 2;
        if (BIAS) { bi0[ni] = bias[n]; bi1[ni] = bias[n + 1]; }
        if (MODE == 2) { wv0[ni] = wv[n]; wv1[ni] = wv[n + 1]; }
    }
    #pragma unroll
    for (int mi = 0; mi < 2; mi++) {
        int r0 = m0 + wm * 32 + mi * 16 + (lane >> 2);
        float rs0 = 0.0f, rs1 = 0.0f;
        #pragma unroll
        for (int ni = 0; ni < 4; ni++) {
            int n = n0 + wn * 32 + ni * 8 + (lane & 3) * 2;
            float x0 = acc[mi][ni][0], x1 = acc[mi][ni][1];
            float x2 = acc[mi][ni][2], x3 = acc[mi][ni][3];
            if (BIAS) { x0 += bi0[ni]; x1 += bi1[ni]; x2 += bi0[ni]; x3 += bi1[ni]; }
            if (SILU) {
                x0 = x0 / (1.0f + __expf(-x0));
                x1 = x1 / (1.0f + __expf(-x1));
                x2 = x2 / (1.0f + __expf(-x2));
                x3 = x3 / (1.0f + __expf(-x3));
            }
            if (MODE == 0) {
                *(float2*)(outF + (size_t)r0 * Ntot + n) = make_float2(x0, x1);
                *(float2*)(outF + (size_t)(r0 + 8) * Ntot + n) = make_float2(x2, x3);
            } else if (MODE == 3) {
                *(__half2*)(outHL + (size_t)r0 * (2 * Ntot) + n) =
                    __halves2half2(__float2half_rn(x0), __float2half_rn(x1));
                *(__half2*)(outHL + (size_t)(r0 + 8) * (2 * Ntot) + n) =
                    __halves2half2(__float2half_rn(x2), __float2half_rn(x3));
            } else {
                rs0 += x0 * wv0[ni] + x1 * wv1[ni];
                rs1 += x2 * wv0[ni] + x3 * wv1[ni];
            }
        }
        if (MODE == 2) {
            rs0 += __shfl_xor_sync(0xffffffffu, rs0, 1);
            rs0 += __shfl_xor_sync(0xffffffffu, rs0, 2);
            rs1 += __shfl_xor_sync(0xffffffffu, rs1, 1);
            rs1 += __shfl_xor_sync(0xffffffffu, rs1, 2);
            if ((lane & 3) == 0) {
                atomicAdd(outF + r0, rs0);
                atomicAdd(outF + r0 + 8, rs1);
            }
        }
    }
}

// ---------------- LayerNorm(mixed) * distfilter -> reg (hi fp16 only) ----------------
__global__ void ln_mult_kernel(const float* __restrict__ ln_g,
                               const float* __restrict__ ln_b) {
    int e = blockIdx.x;
    int tid = threadIdx.x;   // 128 threads, 4 floats each
    __shared__ float sh[4];
    const float* row = g_mixed + (size_t)e * NS;
    float4 x = *(const float4*)(row + tid * 4);
    float s = x.x + x.y + x.z + x.w;
    int lane = tid & 31, wid = tid >> 5;
    #pragma unroll
    for (int o = 16; o; o >>= 1) s += __shfl_xor_sync(0xffffffffu, s, o);
    if (!lane) sh[wid] = s;
    __syncthreads();
    float mu = (sh[0] + sh[1] + sh[2] + sh[3]) * (1.0f / 512.0f);
    float d0 = x.x - mu, d1 = x.y - mu, d2 = x.z - mu, d3 = x.w - mu;
    float s2 = d0 * d0 + d1 * d1 + d2 * d2 + d3 * d3;
    #pragma unroll
    for (int o = 16; o; o >>= 1) s2 += __shfl_xor_sync(0xffffffffu, s2, o);
    __syncthreads();
    if (!lane) sh[wid] = s2;
    __syncthreads();
    float var = (sh[0] + sh[1] + sh[2] + sh[3]) * (1.0f / 512.0f);
    float inv = rsqrtf(var + 1e-5f);
    float4 df = *(const float4*)(g_df + (size_t)e * NS + tid * 4);
    float4 gg = *(const float4*)(ln_g + tid * 4);
    float4 bb = *(const float4*)(ln_b + tid * 4);
    float y0 = (d0 * inv * gg.x + bb.x) * df.x;
    float y1 = (d1 * inv * gg.y + bb.y) * df.y;
    float y2 = (d2 * inv * gg.z + bb.z) * df.z;
    float y3 = (d3 * inv * gg.w + bb.w) * df.w;
    __half2* o = (__half2*)(g_reghl + (size_t)e * 1024 + tid * 4);
    o[0] = __halves2half2(__float2half_rn(y0), __float2half_rn(y1));
    o[1] = __halves2half2(__float2half_rn(y2), __float2half_rn(y3));
}

// ---------------- init output with bias ----------------
__global__ void init_out(float* __restrict__ out, const float* __restrict__ b) {
    int i = blockIdx.x * blockDim.x + threadIdx.x;
    if (i < NEDGES) out[i] = b[0];
}

// ---------------- host launcher ----------------
extern "C" void kernel_launch(void* const* d_in, const int* in_sizes, int n_in,
                              void* d_out, int out_size) {
    const float* nodes  = (const float*)d_in[0];
    const float* pos    = (const float*)d_in[1];
    const float* cell   = (const float*)d_in[2];
    const float* eshift = (const float*)d_in[3];
    const float* W0     = (const float*)d_in[4];
    const float* W1     = (const float*)d_in[5];
    const float* W2     = (const float*)d_in[6];
    const float* ln_g   = (const float*)d_in[7];
    const float* ln_b   = (const float*)d_in[8];
    const float* df_w1  = (const float*)d_in[9];
    const float* df_b1  = (const float*)d_in[10];
    const float* df_w2  = (const float*)d_in[11];
    const float* df_b2  = (const float*)d_in[12];
    const float* mi_w1  = (const float*)d_in[13];
    const float* mi_b1  = (const float*)d_in[14];
    const float* mi_w2  = (const float*)d_in[15];
    const float* mi_b2  = (const float*)d_in[16];
    const float* mo_w   = (const float*)d_in[17];
    const float* mo_b   = (const float*)d_in[18];
    const int* edge_index = (const int*)d_in[19];
    const int* batch_vec  = (const int*)d_in[20];
    float* out = (float*)d_out;

    __half *pEmb, *pH1, *pP, *pReg, *pWcat, *pDf1, *pDf2, *pMi1, *pMi2;
    float *pDf, *pMix;
    cudaGetSymbolAddress((void**)&pEmb,  g_embhl);
    cudaGetSymbolAddress((void**)&pH1,   g_h1hl);
    cudaGetSymbolAddress((void**)&pP,    g_Phl);
    cudaGetSymbolAddress((void**)&pReg,  g_reghl);
    cudaGetSymbolAddress((void**)&pWcat, g_WcatT);
    cudaGetSymbolAddress((void**)&pDf1,  g_df1T);
    cudaGetSymbolAddress((void**)&pDf2,  g_df2T);
    cudaGetSymbolAddress((void**)&pMi1,  g_mi1T);
    cudaGetSymbolAddress((void**)&pMi2,  g_mi2T);
    cudaGetSymbolAddress((void**)&pDf,   g_df);
    cudaGetSymbolAddress((void**)&pMix,  g_mixed);

    cudaFuncSetAttribute(hgemm<3, true, true, 1>,  cudaFuncAttributeMaxDynamicSharedMemorySize, SMEMSZ);
    cudaFuncSetAttribute(hgemm<0, true, false, 1>, cudaFuncAttributeMaxDynamicSharedMemorySize, SMEMSZ);
    cudaFuncSetAttribute(hgemm<0, false, false, 1>,cudaFuncAttributeMaxDynamicSharedMemorySize, SMEMSZ);
    cudaFuncSetAttribute(hgemm<2, true, true, 1>,  cudaFuncAttributeMaxDynamicSharedMemorySize, SMEMSZ);

    // prep (R15 tail, proven)
    geom_kernel<<<(NEDGES + 255) / 256, 256>>>(pos, cell, eshift, edge_index, batch_vec);
    emb_kernel<<<NEDGES, 256>>>();
    wcat_kernel<<<(KP * NS + 255) / 256, 256>>>(W0, W1, W2);
    pbuild_kernel<<<NEDGES, 128>>>(nodes, edge_index);
    wt_convert_hi<<<(256 * 1024 + 255) / 256, 256>>>(df_w1, pDf1, 256, 1024);
    wt_convert_hi<<<(1024 * 512 + 255) / 256, 256>>>(df_w2, pDf2, 1024, 512);
    wt_convert_hi<<<(512 * 1024 + 255) / 256, 256>>>(mi_w1, pMi1, 512, 1024);
    wt_convert_hi<<<(1024 * 1024 + 255) / 256, 256>>>(mi_w2, pMi2, 1024, 1024);
    init_out<<<(NEDGES + 255) / 256, 256>>>(out, mo_b);

    // grid: (Ntot/128, NEDGES/64)
    // G1 (fp16): h1 = silu(emb @ df_w1 + b1)   [E x 1024] -> hi plane
    hgemm<3, true, true, 1><<<dim3(8, NEDGES / 64), 256, SMEMSZ>>>(pEmb, pDf1, df_b1, nullptr, nullptr, pH1, 256, 1024);
    // G2 (fp16): df = h1 @ df_w2 + b2          [E x 512] fp32
    hgemm<0, true, false, 1><<<dim3(4, NEDGES / 64), 256, SMEMSZ>>>(pH1, pDf2, df_b2, nullptr, pDf, nullptr, 1024, 512);
    // G3 (fp16): mixed = P @ Wcat              [E x 512] fp32
    hgemm<0, false, false, 1><<<dim3(4, NEDGES / 64), 256, SMEMSZ>>>(pP, pWcat, nullptr, nullptr, pMix, nullptr, 1344, 512);
    // LN * distfilter -> reg (hi only)
    ln_mult_kernel<<<NEDGES, 128>>>(ln_g, ln_b);
    // G4 (fp16): h = silu(reg @ mi_w1 + b)     [E x 1024] -> hi plane
    hgemm<3, true, true, 1><<<dim3(8, NEDGES / 64), 256, SMEMSZ>>>(pReg, pMi1, mi_b1, nullptr, nullptr, pH1, 512, 1024);
    // G5 (fp16): out += silu(h @ mi_w2 + b) . mo_w   (fused head)
    hgemm<2, true, true, 1><<<dim3(8, NEDGES / 64), 256, SMEMSZ>>>(pH1, pMi2, mi_b2, mo_w, out, nullptr, 1024, 1024);
}

// round 17
// speedup vs baseline: 1.0480x; 1.0480x over previous
#include <cuda_runtime.h>
#include <cuda_fp16.h>
#include <math.h>
#include <stdint.h>

#define NEDGES 131072
#define FEAT   120
#define NS     512
#define KP     1344
#define MBLK   1024      // NEDGES/128

// -------- static device scratch (allocation-free rule) --------
__device__ float  g_r[NEDGES];
__device__ __half g_embhl[(size_t)NEDGES * 512];    // [E][hi256|pad]
__device__ __half g_h1hl [(size_t)NEDGES * 2048];   // [E][hi1024|pad]
__device__ float  g_df   [(size_t)NEDGES * NS];
__device__ __half g_Phl  [(size_t)NEDGES * 2688];   // [E][hi1344|pad]
__device__ float  g_mixed[(size_t)NEDGES * NS];
__device__ __half g_reghl[(size_t)NEDGES * 1024];   // [E][hi512|pad]
// transposed weights: [N rows][hiK|loK] (lo planes unused, stride kept)
__device__ __half g_WcatT[(size_t)512  * 2688];
__device__ __half g_df1T [(size_t)1024 * 512];
__device__ __half g_df2T [(size_t)512  * 2048];
__device__ __half g_mi1T [(size_t)1024 * 1024];
__device__ __half g_mi2T [(size_t)1024 * 2048];

__device__ __forceinline__ uint32_t smem_u32(const void* p) {
    uint32_t a;
    asm("{ .reg .u64 t; cvta.to.shared.u64 t, %1; cvt.u32.u64 %0, t; }" : "=r"(a) : "l"(p));
    return a;
}
__device__ __forceinline__ void cp16(uint32_t s, const void* g) {
    asm volatile("cp.async.cg.shared.global [%0], [%1], 16;" :: "r"(s), "l"(g) : "memory");
}
__device__ __forceinline__ void ldm4(uint32_t* r, uint32_t addr) {
    asm volatile("ldmatrix.sync.aligned.m8n8.x4.shared.b16 {%0,%1,%2,%3}, [%4];"
                 : "=r"(r[0]), "=r"(r[1]), "=r"(r[2]), "=r"(r[3]) : "r"(addr));
}
__device__ __forceinline__ void mma16816(float* c, const uint32_t* a, uint32_t b0, uint32_t b1) {
    asm volatile("mma.sync.aligned.m16n8k16.row.col.f32.f16.f16.f32 "
                 "{%0,%1,%2,%3}, {%4,%5,%6,%7}, {%8,%9}, {%0,%1,%2,%3};"
                 : "+f"(c[0]), "+f"(c[1]), "+f"(c[2]), "+f"(c[3])
                 : "r"(a[0]), "r"(a[1]), "r"(a[2]), "r"(a[3]), "r"(b0), "r"(b1));
}

// ---------------- kernel: edge geometry -> r ----------------
__global__ void geom_kernel(const float* __restrict__ pos,
                            const float* __restrict__ cell,
                            const float* __restrict__ shift,
                            const int* __restrict__ ei,
                            const int* __restrict__ bvec) {
    int e = blockIdx.x * blockDim.x + threadIdx.x;
    if (e >= NEDGES) return;
    int src = ei[e];
    int dst = ei[NEDGES + e];
    int b = bvec[src];
    const float* C = cell + (size_t)b * 9;
    float s0 = shift[e * 3 + 0], s1 = shift[e * 3 + 1], s2 = shift[e * 3 + 2];
    float t0 = s0 * C[0] + s1 * C[3] + s2 * C[6];
    float t1 = s0 * C[1] + s1 * C[4] + s2 * C[7];
    float t2 = s0 * C[2] + s1 * C[5] + s2 * C[8];
    float dx = pos[dst * 3 + 0] - pos[src * 3 + 0] + t0;
    float dy = pos[dst * 3 + 1] - pos[src * 3 + 1] + t1;
    float dz = pos[dst * 3 + 2] - pos[src * 3 + 2] + t2;
    float dist = sqrtf(dx * dx + dy * dy + dz * dz);
    g_r[e] = 1.0f / (dist + 1e-6f);
}

// ---------------- radial embedding (hi fp16 only) ----------------
__global__ void emb_kernel() {
    int e = blockIdx.x;
    int k = threadIdx.x;   // 0..255
    float r = g_r[e];
    float amp = sqrtf(2.0f / 7.0f) / r;
    float ph = 3.14159265358979323846f * r / 7.0f;
    float x = amp * sinf((float)(k + 1) * ph);
    g_embhl[(size_t)e * 512 + k] = __float2half_rn(x);
}

// ---------------- symmetrized Wcat, transposed (hi only) ----------------
__global__ void wcat_kernel(const float* __restrict__ W0,
                            const float* __restrict__ W1,
                            const float* __restrict__ W2) {
    int idx = blockIdx.x * blockDim.x + threadIdx.x;
    if (idx >= KP * NS) return;
    int k = idx >> 9;
    int n = idx & 511;
    float fan = sqrtf(1344.0f);
    float v;
    if (k < 1024) {
        int u = k >> 5, vv = k & 31;
        v = (W0[(size_t)(u * 32 + vv) * NS + n] + W0[(size_t)(vv * 32 + u) * NS + n]) * (0.5f / fan);
    } else if (k < 1280) {
        int t = k - 1024;
        int u = t >> 4, vv = t & 15;
        v = (W1[(size_t)(u * 16 + vv) * NS + n] + W1[(size_t)(vv * 16 + u) * NS + n]) * (0.5f / (fan * sqrtf(3.0f)));
    } else {
        int t = k - 1280;
        int u = t >> 3, vv = t & 7;
        v = (W2[(size_t)(u * 8 + vv) * NS + n] + W2[(size_t)(vv * 8 + u) * NS + n]) * (0.5f / (fan * sqrtf(5.0f)));
    }
    g_WcatT[(size_t)n * 2688 + k] = __float2half_rn(v);
}

// ---------------- merged weight transposes (4 matrices, one launch) ----------------
// seg 0: df1T K=256  N=1024 (262144)
// seg 1: df2T K=1024 N=512  (524288)
// seg 2: mi1T K=512  N=1024 (524288)
// seg 3: mi2T K=1024 N=1024 (1048576)
#define WT_END0 262144
#define WT_END1 (WT_END0 + 524288)
#define WT_END2 (WT_END1 + 524288)
#define WT_END3 (WT_END2 + 1048576)
__global__ void wtall_kernel(const float* __restrict__ df_w1,
                             const float* __restrict__ df_w2,
                             const float* __restrict__ mi_w1,
                             const float* __restrict__ mi_w2) {
    int idx = blockIdx.x * blockDim.x + threadIdx.x;
    if (idx >= WT_END3) return;
    if (idx < WT_END0) {
        int n = idx >> 8, k = idx & 255;
        g_df1T[(size_t)n * 512 + k] = __float2half_rn(df_w1[(size_t)k * 1024 + n]);
    } else if (idx < WT_END1) {
        int i = idx - WT_END0;
        int n = i >> 10, k = i & 1023;
        g_df2T[(size_t)n * 2048 + k] = __float2half_rn(df_w2[(size_t)k * 512 + n]);
    } else if (idx < WT_END2) {
        int i = idx - WT_END1;
        int n = i >> 9, k = i & 511;
        g_mi1T[(size_t)n * 1024 + k] = __float2half_rn(mi_w1[(size_t)k * 1024 + n]);
    } else {
        int i = idx - WT_END2;
        int n = i >> 10, k = i & 1023;
        g_mi2T[(size_t)n * 2048 + k] = __float2half_rn(mi_w2[(size_t)k * 1024 + n]);
    }
}

// ---------------- outer products P (hi only, half2-vectorized; bit-identical math) ----------------
__global__ void pbuild_kernel(const float* __restrict__ nodes,
                              const int* __restrict__ ei) {
    int e = blockIdx.x;
    int tid = threadIdx.x;   // 128
    __shared__ float xs[FEAT];
    __shared__ float xd[FEAT];
    int src = ei[e];
    int dst = ei[NEDGES + e];
    if (tid < FEAT) {
        xs[tid] = nodes[(size_t)src * FEAT + tid];
        xd[tid] = nodes[(size_t)dst * FEAT + tid];
    }
    __syncthreads();
    __half2* Pe2 = (__half2*)(g_Phl + (size_t)e * 2688);
    // 672 half2 elements; pairs (2i, 2i+1) never straddle segment boundaries
    #pragma unroll
    for (int it = 0; it < 6; it++) {
        int p = tid + it * 128;
        if (p >= 672) break;
        int idx = p << 1;
        float v0, v1;
        if (idx < 1024) {
            int u = idx >> 5, w = idx & 31;
            float a = xs[u];
            v0 = a * xd[w];
            v1 = a * xd[w + 1];
        } else if (idx < 1280) {
            int t = idx - 1024;
            int u = t >> 4, w = t & 15;
            const float* a = xs + 32 + u * 3;
            const float* b0 = xd + 32 + w * 3;
            v0 = a[0] * b0[0] + a[1] * b0[1] + a[2] * b0[2];
            const float* b1 = b0 + 3;
            v1 = a[0] * b1[0] + a[1] * b1[1] + a[2] * b1[2];
        } else {
            int t = idx - 1280;
            int u = t >> 3, w = t & 7;
            const float* a = xs + 80 + u * 5;
            const float* b0 = xd + 80 + w * 5;
            v0 = a[0] * b0[0] + a[1] * b0[1] + a[2] * b0[2] + a[3] * b0[3] + a[4] * b0[4];
            const float* b1 = b0 + 5;
            v1 = a[0] * b1[0] + a[1] * b1[1] + a[2] * b1[2] + a[3] * b1[3] + a[4] * b1[4];
        }
        Pe2[p] = __halves2half2(__float2half_rn(v0), __float2half_rn(v1));
    }
}

// ====== HMMA GEMM (R15 config, proven best): CTA 128x128, 8 warps of 32x64, BK=64, 3 stages, occ 2 ======
// Pure fp16 (SPLIT=1). A [M][K stride 2K], B [N][K stride 2K].
// MODE: 0 = fp32 out, 2 = fused head, 3 = fp16 hi plane only
#define STAGE_BYTES 32768
#define SMEMSZ (3 * STAGE_BYTES)

template<int MODE, bool BIAS, bool SILU, int SPLIT>
__global__ __launch_bounds__(256, 2)
void hgemm(const __half* __restrict__ A, const __half* __restrict__ B,
           const float* __restrict__ bias, const float* __restrict__ wv,
           float* __restrict__ outF, __half* __restrict__ outHL,
           int K, int Ntot) {
    extern __shared__ __align__(16) char smem[];
    const uint32_t sbase = smem_u32(smem);
    const int tid = threadIdx.x;
    const int lane = tid & 31;
    const int wid = tid >> 5;
    const int wm = wid & 3;        // 4 warps along M (32 rows each)
    const int wn = wid >> 2;       // 2 warps along N (64 cols each)
    const int m0 = blockIdx.y << 7;
    const int n0 = blockIdx.x << 7;
    const int A2K = 2 * K;
    const size_t strB = (size_t)A2K * sizeof(__half);
    const int nsuper = (SPLIT * K) >> 6;

    float acc[2][8][4];
    #pragma unroll
    for (int i = 0; i < 2; i++)
        #pragma unroll
        for (int j = 0; j < 8; j++)
            #pragma unroll
            for (int q = 0; q < 4; q++) acc[i][j][q] = 0.0f;

    auto load_sub = [&](int s, int h, int c) {
        int kg = c << 5;
        int seg = kg / K;
        int kin = kg - seg * K;
        int acol = kin + (seg == 2 ? K : 0);
        int bcol = kin + (seg == 1 ? K : 0);
        const char* Ag = (const char*)(A + (size_t)m0 * A2K + acol);
        const char* Bg = (const char*)(B + (size_t)n0 * A2K + bcol);
        uint32_t sA = sbase + (uint32_t)(s * STAGE_BYTES + h * 16384);
        uint32_t sB = sA + 8192;
        #pragma unroll
        for (int i = 0; i < 2; i++) {
            int idx = tid + (i << 8);      // 0..511
            int row = idx >> 2;
            int ch = idx & 3;
            uint32_t sw = (uint32_t)((ch ^ ((row >> 1) & 3)) << 4);
            cp16(sA + (uint32_t)(row * 64) + sw, Ag + (size_t)row * strB + ch * 16);
            cp16(sB + (uint32_t)(row * 64) + sw, Bg + (size_t)row * strB + ch * 16);
        }
    };
    auto load_super = [&](int s, int cs) {
        load_sub(s, 0, 2 * cs);
        load_sub(s, 1, 2 * cs + 1);
    };

    auto compute_sub = [&](int s, int h) {
        const uint32_t sA = sbase + (uint32_t)(s * STAGE_BYTES + h * 16384);
        const uint32_t sB = sA + 8192;
        #pragma unroll
        for (int kk = 0; kk < 2; kk++) {
            uint32_t a[2][4];
            #pragma unroll
            for (int mi = 0; mi < 2; mi++) {
                int r = wm * 32 + mi * 16 + (lane & 15);
                int ch = 2 * kk + (lane >> 4);
                ldm4(a[mi], sA + (uint32_t)(r * 64 + ((ch ^ ((r >> 1) & 3)) << 4)));
            }
            uint32_t b[4][4];
            #pragma unroll
            for (int nh = 0; nh < 4; nh++) {
                int r = wn * 64 + nh * 16 + (lane & 15);
                int ch = 2 * kk + (lane >> 4);
                ldm4(b[nh], sB + (uint32_t)(r * 64 + ((ch ^ ((r >> 1) & 3)) << 4)));
            }
            #pragma unroll
            for (int mi = 0; mi < 2; mi++)
                #pragma unroll
                for (int ni = 0; ni < 8; ni++)
                    mma16816(acc[mi][ni], a[mi], b[ni >> 1][ni & 1], b[ni >> 1][(ni & 1) + 2]);
        }
    };

    load_super(0, 0);
    asm volatile("cp.async.commit_group;" ::: "memory");
    load_super(1, 1);
    asm volatile("cp.async.commit_group;" ::: "memory");

    for (int cs = 0; cs < nsuper; cs++) {
        asm volatile("cp.async.wait_group 1;" ::: "memory");
        __syncthreads();
        if (cs + 2 < nsuper) load_super((cs + 2) % 3, cs + 2);
        asm volatile("cp.async.commit_group;" ::: "memory");
        compute_sub(cs % 3, 0);
        compute_sub(cs % 3, 1);
    }

    // ---------------- epilogue: direct register -> global ----------------
    float bi0[8], bi1[8], wv0[8], wv1[8];
    #pragma unroll
    for (int ni = 0; ni < 8; ni++) {
        int n = n0 + wn * 64 + ni * 8 + (lane & 3) * 2;
        if (BIAS) { bi0[ni] = bias[n]; bi1[ni] = bias[n + 1]; }
        if (MODE == 2) { wv0[ni] = wv[n]; wv1[ni] = wv[n + 1]; }
    }
    #pragma unroll
    for (int mi = 0; mi < 2; mi++) {
        int r0 = m0 + wm * 32 + mi * 16 + (lane >> 2);
        float rs0 = 0.0f, rs1 = 0.0f;
        #pragma unroll
        for (int ni = 0; ni < 8; ni++) {
            int n = n0 + wn * 64 + ni * 8 + (lane & 3) * 2;
            float x0 = acc[mi][ni][0], x1 = acc[mi][ni][1];
            float x2 = acc[mi][ni][2], x3 = acc[mi][ni][3];
            if (BIAS) { x0 += bi0[ni]; x1 += bi1[ni]; x2 += bi0[ni]; x3 += bi1[ni]; }
            if (SILU) {
                x0 = x0 / (1.0f + __expf(-x0));
                x1 = x1 / (1.0f + __expf(-x1));
                x2 = x2 / (1.0f + __expf(-x2));
                x3 = x3 / (1.0f + __expf(-x3));
            }
            if (MODE == 0) {
                *(float2*)(outF + (size_t)r0 * Ntot + n) = make_float2(x0, x1);
                *(float2*)(outF + (size_t)(r0 + 8) * Ntot + n) = make_float2(x2, x3);
            } else if (MODE == 3) {
                *(__half2*)(outHL + (size_t)r0 * (2 * Ntot) + n) =
                    __halves2half2(__float2half_rn(x0), __float2half_rn(x1));
                *(__half2*)(outHL + (size_t)(r0 + 8) * (2 * Ntot) + n) =
                    __halves2half2(__float2half_rn(x2), __float2half_rn(x3));
            } else {
                rs0 += x0 * wv0[ni] + x1 * wv1[ni];
                rs1 += x2 * wv0[ni] + x3 * wv1[ni];
            }
        }
        if (MODE == 2) {
            rs0 += __shfl_xor_sync(0xffffffffu, rs0, 1);
            rs0 += __shfl_xor_sync(0xffffffffu, rs0, 2);
            rs1 += __shfl_xor_sync(0xffffffffu, rs1, 1);
            rs1 += __shfl_xor_sync(0xffffffffu, rs1, 2);
            if ((lane & 3) == 0) {
                atomicAdd(outF + r0, rs0);
                atomicAdd(outF + r0 + 8, rs1);
            }
        }
    }
}

// ---------------- LayerNorm(mixed) * distfilter -> reg (hi fp16 only) ----------------
__global__ void ln_mult_kernel(const float* __restrict__ ln_g,
                               const float* __restrict__ ln_b) {
    int e = blockIdx.x;
    int tid = threadIdx.x;   // 128 threads, 4 floats each
    __shared__ float sh[4];
    const float* row = g_mixed + (size_t)e * NS;
    float4 x = *(const float4*)(row + tid * 4);
    float s = x.x + x.y + x.z + x.w;
    int lane = tid & 31, wid = tid >> 5;
    #pragma unroll
    for (int o = 16; o; o >>= 1) s += __shfl_xor_sync(0xffffffffu, s, o);
    if (!lane) sh[wid] = s;
    __syncthreads();
    float mu = (sh[0] + sh[1] + sh[2] + sh[3]) * (1.0f / 512.0f);
    float d0 = x.x - mu, d1 = x.y - mu, d2 = x.z - mu, d3 = x.w - mu;
    float s2 = d0 * d0 + d1 * d1 + d2 * d2 + d3 * d3;
    #pragma unroll
    for (int o = 16; o; o >>= 1) s2 += __shfl_xor_sync(0xffffffffu, s2, o);
    __syncthreads();
    if (!lane) sh[wid] = s2;
    __syncthreads();
    float var = (sh[0] + sh[1] + sh[2] + sh[3]) * (1.0f / 512.0f);
    float inv = rsqrtf(var + 1e-5f);
    float4 df = *(const float4*)(g_df + (size_t)e * NS + tid * 4);
    float4 gg = *(const float4*)(ln_g + tid * 4);
    float4 bb = *(const float4*)(ln_b + tid * 4);
    float y0 = (d0 * inv * gg.x + bb.x) * df.x;
    float y1 = (d1 * inv * gg.y + bb.y) * df.y;
    float y2 = (d2 * inv * gg.z + bb.z) * df.z;
    float y3 = (d3 * inv * gg.w + bb.w) * df.w;
    __half2* o = (__half2*)(g_reghl + (size_t)e * 1024 + tid * 4);
    o[0] = __halves2half2(__float2half_rn(y0), __float2half_rn(y1));
    o[1] = __halves2half2(__float2half_rn(y2), __float2half_rn(y3));
}

// ---------------- init output with bias ----------------
__global__ void init_out(float* __restrict__ out, const float* __restrict__ b) {
    int i = blockIdx.x * blockDim.x + threadIdx.x;
    if (i < NEDGES) out[i] = b[0];
}

// ---------------- host launcher ----------------
extern "C" void kernel_launch(void* const* d_in, const int* in_sizes, int n_in,
                              void* d_out, int out_size) {
    const float* nodes  = (const float*)d_in[0];
    const float* pos    = (const float*)d_in[1];
    const float* cell   = (const float*)d_in[2];
    const float* eshift = (const float*)d_in[3];
    const float* W0     = (const float*)d_in[4];
    const float* W1     = (const float*)d_in[5];
    const float* W2     = (const float*)d_in[6];
    const float* ln_g   = (const float*)d_in[7];
    const float* ln_b   = (const float*)d_in[8];
    const float* df_w1  = (const float*)d_in[9];
    const float* df_b1  = (const float*)d_in[10];
    const float* df_w2  = (const float*)d_in[11];
    const float* df_b2  = (const float*)d_in[12];
    const float* mi_w1  = (const float*)d_in[13];
    const float* mi_b1  = (const float*)d_in[14];
    const float* mi_w2  = (const float*)d_in[15];
    const float* mi_b2  = (const float*)d_in[16];
    const float* mo_w   = (const float*)d_in[17];
    const float* mo_b   = (const float*)d_in[18];
    const int* edge_index = (const int*)d_in[19];
    const int* batch_vec  = (const int*)d_in[20];
    float* out = (float*)d_out;

    __half *pEmb, *pH1, *pP, *pReg, *pWcat, *pDf1, *pDf2, *pMi1, *pMi2;
    float *pDf, *pMix;
    cudaGetSymbolAddress((void**)&pEmb,  g_embhl);
    cudaGetSymbolAddress((void**)&pH1,   g_h1hl);
    cudaGetSymbolAddress((void**)&pP,    g_Phl);
    cudaGetSymbolAddress((void**)&pReg,  g_reghl);
    cudaGetSymbolAddress((void**)&pWcat, g_WcatT);
    cudaGetSymbolAddress((void**)&pDf1,  g_df1T);
    cudaGetSymbolAddress((void**)&pDf2,  g_df2T);
    cudaGetSymbolAddress((void**)&pMi1,  g_mi1T);
    cudaGetSymbolAddress((void**)&pMi2,  g_mi2T);
    cudaGetSymbolAddress((void**)&pDf,   g_df);
    cudaGetSymbolAddress((void**)&pMix,  g_mixed);

    cudaFuncSetAttribute(hgemm<3, true, true, 1>,  cudaFuncAttributeMaxDynamicSharedMemorySize, SMEMSZ);
    cudaFuncSetAttribute(hgemm<0, true, false, 1>, cudaFuncAttributeMaxDynamicSharedMemorySize, SMEMSZ);
    cudaFuncSetAttribute(hgemm<0, false, false, 1>,cudaFuncAttributeMaxDynamicSharedMemorySize, SMEMSZ);
    cudaFuncSetAttribute(hgemm<2, true, true, 1>,  cudaFuncAttributeMaxDynamicSharedMemorySize, SMEMSZ);

    // prep
    geom_kernel<<<(NEDGES + 255) / 256, 256>>>(pos, cell, eshift, edge_index, batch_vec);
    emb_kernel<<<NEDGES, 256>>>();
    wcat_kernel<<<(KP * NS + 255) / 256, 256>>>(W0, W1, W2);
    pbuild_kernel<<<NEDGES, 128>>>(nodes, edge_index);
    wtall_kernel<<<(WT_END3 + 255) / 256, 256>>>(df_w1, df_w2, mi_w1, mi_w2);
    init_out<<<(NEDGES + 255) / 256, 256>>>(out, mo_b);

    // G1 (fp16): h1 = silu(emb @ df_w1 + b1)   [E x 1024] -> hi plane
    hgemm<3, true, true, 1><<<dim3(8, MBLK), 256, SMEMSZ>>>(pEmb, pDf1, df_b1, nullptr, nullptr, pH1, 256, 1024);
    // G2 (fp16): df = h1 @ df_w2 + b2          [E x 512] fp32
    hgemm<0, true, false, 1><<<dim3(4, MBLK), 256, SMEMSZ>>>(pH1, pDf2, df_b2, nullptr, pDf, nullptr, 1024, 512);
    // G3 (fp16): mixed = P @ Wcat              [E x 512] fp32
    hgemm<0, false, false, 1><<<dim3(4, MBLK), 256, SMEMSZ>>>(pP, pWcat, nullptr, nullptr, pMix, nullptr, 1344, 512);
    // LN * distfilter -> reg (hi only)
    ln_mult_kernel<<<NEDGES, 128>>>(ln_g, ln_b);
    // G4 (fp16): h = silu(reg @ mi_w1 + b)     [E x 1024] -> hi plane
    hgemm<3, true, true, 1><<<dim3(8, MBLK), 256, SMEMSZ>>>(pReg, pMi1, mi_b1, nullptr, nullptr, pH1, 512, 1024);
    // G5 (fp16): out += silu(h @ mi_w2 + b) . mo_w   (fused head)
    hgemm<2, true, true, 1><<<dim3(8, MBLK), 256, SMEMSZ>>>(pH1, pMi2, mi_b2, mo_w, out, nullptr, 1024, 1024);
}